// round 3
// baseline (speedup 1.0000x reference)
#include <cuda_runtime.h>

// Problem constants
#define FM_H 38
#define FM_W 50
#define FM_C 512
#define N_ROI 512
#define POOL 7          // 7x7 pooled output
#define CROP 14         // 14x14 crop grid (2x2 per pooled cell)

__device__ __forceinline__ float4 lerp4(float4 a, float4 b, float w) {
    float4 r;
    r.x = a.x * (1.0f - w) + b.x * w;
    r.y = a.y * (1.0f - w) + b.y * w;
    r.z = a.z * (1.0f - w) + b.z * w;
    r.w = a.w * (1.0f - w) + b.w * w;
    return r;
}

__device__ __forceinline__ float4 max4(float4 a, float4 b) {
    float4 r;
    r.x = fmaxf(a.x, b.x);
    r.y = fmaxf(a.y, b.y);
    r.z = fmaxf(a.z, b.z);
    r.w = fmaxf(a.w, b.w);
    return r;
}

// One block per (pooled_row, roi). 128 threads x float4 = 512 channels.
// Streams the 14 crop columns left->right, caching the y-interpolated
// column vectors (Ya,Yb) for the two current tap columns in registers,
// reusing them when x0 advances by 0 or 1 (the common case), and
// dedup'ing the <=4 y-tap rows per fresh column (typically 3 distinct).
__global__ __launch_bounds__(128) void roi_pool_kernel(
    const float* __restrict__ fm,     // [38,50,512]
    const float* __restrict__ rois,   // [512,5] (0, x1, y1, x2, y2)
    float* __restrict__ out)          // [512,7,7,512]
{
    const int py  = blockIdx.x;       // 0..6
    const int roi = blockIdx.y;       // 0..511
    const int t   = threadIdx.x;      // channel group: c = 4*t

    const float* r = rois + roi * 5;
    const float x1n = r[1] * (1.0f / 800.0f);
    const float y1n = r[2] * (1.0f / 600.0f);
    const float x2n = r[3] * (1.0f / 800.0f);
    const float y2n = r[4] * (1.0f / 600.0f);
    const float dy = y2n - y1n;
    const float dx = x2n - x1n;

    // y taps for the two crop rows of this pooled row
    int ro_a0, ro_a1, ro_b0, ro_b1;   // fm row offsets (row * FM_W)
    int y0a, y1a, y0b, y1b;
    float wya, wyb;
    {
        const float tya = (float)(2 * py) * (1.0f / 13.0f);
        const float ysa = (y1n + tya * dy) * (float)(FM_H - 1);
        const float yfa = floorf(ysa);
        int y0 = (int)yfa; y0 = min(max(y0, 0), FM_H - 1);
        y0a = y0; y1a = min(y0 + 1, FM_H - 1); wya = ysa - yfa;

        const float tyb = (float)(2 * py + 1) * (1.0f / 13.0f);
        const float ysb = (y1n + tyb * dy) * (float)(FM_H - 1);
        const float yfb = floorf(ysb);
        int y0x = (int)yfb; y0x = min(max(y0x, 0), FM_H - 1);
        y0b = y0x; y1b = min(y0x + 1, FM_H - 1); wyb = ysb - yfb;

        ro_a0 = y0a * FM_W; ro_a1 = y1a * FM_W;
        ro_b0 = y0b * FM_W; ro_b1 = y1b * FM_W;
    }

    const float4* fm4 = (const float4*)fm;   // [(y*50 + x)*128 + t]

    // Load one fm column c: fetch <=4 rows with dedup, y-interpolate.
    auto loadcol = [&](int c, float4& Ra, float4& Rb) {
        const float4 va0 = fm4[(ro_a0 + c) * 128 + t];
        const float4 va1 = (y1a == y0a) ? va0 : fm4[(ro_a1 + c) * 128 + t];
        float4 vb0;
        if (y0b == y1a)      vb0 = va1;
        else if (y0b == y0a) vb0 = va0;
        else                 vb0 = fm4[(ro_b0 + c) * 128 + t];
        float4 vb1;
        if (y1b == y0b)      vb1 = vb0;
        else if (y1b == y1a) vb1 = va1;
        else                 vb1 = fm4[(ro_b1 + c) * 128 + t];
        Ra = lerp4(va0, va1, wya);
        Rb = lerp4(vb0, vb1, wyb);
    };

    int prev_x0 = -1000000;
    float4 Ya0, Ya1, Yb0, Yb1;
    float4 acc;

    float4* out4 = (float4*)out;
    const int out_base = ((roi * POOL + py) * POOL) * 128 + t;

#pragma unroll
    for (int ix = 0; ix < CROP; ++ix) {
        const float txv = (float)ix * (1.0f / 13.0f);
        const float xs = (x1n + txv * dx) * (float)(FM_W - 1);
        const float xf = floorf(xs);
        int x0 = (int)xf; x0 = min(max(x0, 0), FM_W - 1);
        const int x1 = min(x0 + 1, FM_W - 1);
        const float wx = xs - xf;

        if (x0 == prev_x0) {
            // both columns cached — nothing to load
        } else if (x0 == prev_x0 + 1) {
            Ya0 = Ya1; Yb0 = Yb1;
            loadcol(x1, Ya1, Yb1);
        } else {
            loadcol(x0, Ya0, Yb0);
            if (x1 == x0) { Ya1 = Ya0; Yb1 = Yb0; }
            else          loadcol(x1, Ya1, Yb1);
        }
        prev_x0 = x0;

        const float4 va = lerp4(Ya0, Ya1, wx);
        const float4 vb = lerp4(Yb0, Yb1, wx);
        const float4 m = max4(va, vb);

        if ((ix & 1) == 0) {
            acc = m;
        } else {
            acc = max4(acc, m);
            out4[out_base + (ix >> 1) * 128] = acc;
        }
    }
}

extern "C" void kernel_launch(void* const* d_in, const int* in_sizes, int n_in,
                              void* d_out, int out_size)
{
    const float* fm   = (const float*)d_in[0];   // feature_maps [1,38,50,512]
    const float* rois = (const float*)d_in[1];   // [512,5]
    float* out = (float*)d_out;                  // [1,512,7,7,512]

    dim3 grid(POOL, N_ROI);
    roi_pool_kernel<<<grid, 128>>>(fm, rois, out);
}

// round 4
// speedup vs baseline: 1.4334x; 1.4334x over previous
#include <cuda_runtime.h>

#define FM_H 38
#define FM_W 50
#define N_ROI 512
#define POOL 7
#define CROP 14

__device__ __forceinline__ float4 quad4(float4 a, float4 b, float4 c, float4 d,
                                        float w0, float w1, float w2, float w3) {
    float4 r;
    r.x = fmaf(d.x, w3, fmaf(c.x, w2, fmaf(b.x, w1, a.x * w0)));
    r.y = fmaf(d.y, w3, fmaf(c.y, w2, fmaf(b.y, w1, a.y * w0)));
    r.z = fmaf(d.z, w3, fmaf(c.z, w2, fmaf(b.z, w1, a.z * w0)));
    r.w = fmaf(d.w, w3, fmaf(c.w, w2, fmaf(b.w, w1, a.w * w0)));
    return r;
}

__device__ __forceinline__ float4 max4(float4 a, float4 b) {
    float4 r;
    r.x = fmaxf(a.x, b.x);
    r.y = fmaxf(a.y, b.y);
    r.z = fmaxf(a.z, b.z);
    r.w = fmaxf(a.w, b.w);
    return r;
}

// One block per (pooled_row, roi). 128 threads x float4 = 512 channels.
// Amortizes ROI + y-tap setup over 7 pooled cells; each cell does 16
// unconditional batched float4 tap loads and a 4-term weighted sum per
// crop point (weights precomputed as block-uniform scalars).
__global__ __launch_bounds__(128) void roi_pool_kernel(
    const float* __restrict__ fm,     // [38,50,512]
    const float* __restrict__ rois,   // [512,5] (0, x1, y1, x2, y2)
    float* __restrict__ out)          // [512,7,7,512]
{
    const int py  = blockIdx.x;       // 0..6
    const int roi = blockIdx.y;       // 0..511
    const int t   = threadIdx.x;      // channel group: c = 4*t

    const float* r = rois + roi * 5;
    const float x1n = r[1] * (1.0f / 800.0f);
    const float y1n = r[2] * (1.0f / 600.0f);
    const float x2n = r[3] * (1.0f / 800.0f);
    const float y2n = r[4] * (1.0f / 600.0f);
    const float dy = y2n - y1n;
    const float dx = x2n - x1n;

    // y taps for the two crop rows of this pooled row (block-uniform)
    int ra0, ra1, rb0, rb1;           // fm row offsets (row * FM_W)
    float wya, wyb;
    {
        const float tya = (float)(2 * py) * (1.0f / 13.0f);
        const float ysa = (y1n + tya * dy) * (float)(FM_H - 1);
        const float yfa = floorf(ysa);
        int y0 = (int)yfa; y0 = min(max(y0, 0), FM_H - 1);
        ra0 = y0 * FM_W;
        ra1 = min(y0 + 1, FM_H - 1) * FM_W;
        wya = ysa - yfa;

        const float tyb = (float)(2 * py + 1) * (1.0f / 13.0f);
        const float ysb = (y1n + tyb * dy) * (float)(FM_H - 1);
        const float yfb = floorf(ysb);
        int y1 = (int)yfb; y1 = min(max(y1, 0), FM_H - 1);
        rb0 = y1 * FM_W;
        rb1 = min(y1 + 1, FM_H - 1) * FM_W;
        wyb = ysb - yfb;
    }
    const float uya = 1.0f - wya;
    const float uyb = 1.0f - wyb;

    const float4* fmt = (const float4*)fm + t;          // thread base
    float4* outp = (float4*)out + (size_t)((roi * POOL + py) * POOL) * 128 + t;

#pragma unroll
    for (int px = 0; px < POOL; ++px) {
        // x taps for the two crop cols of this pooled cell (block-uniform)
        int x0a, x1a, x0b, x1b;
        float wxa, wxb;
        {
            const float txa = (float)(2 * px) * (1.0f / 13.0f);
            const float xsa = (x1n + txa * dx) * (float)(FM_W - 1);
            const float xfa = floorf(xsa);
            int x0 = (int)xfa; x0 = min(max(x0, 0), FM_W - 1);
            x0a = x0; x1a = min(x0 + 1, FM_W - 1); wxa = xsa - xfa;

            const float txb = (float)(2 * px + 1) * (1.0f / 13.0f);
            const float xsb = (x1n + txb * dx) * (float)(FM_W - 1);
            const float xfb = floorf(xsb);
            int x1 = (int)xfb; x1 = min(max(x1, 0), FM_W - 1);
            x0b = x1; x1b = min(x1 + 1, FM_W - 1); wxb = xsb - xfb;
        }
        const float uxa = 1.0f - wxa;
        const float uxb = 1.0f - wxb;

        // 16 unconditional tap loads (fully independent -> high MLP)
        const float4 vA0a = fmt[(ra0 + x0a) * 128];
        const float4 vA1a = fmt[(ra0 + x1a) * 128];
        const float4 vA0b = fmt[(ra0 + x0b) * 128];
        const float4 vA1b = fmt[(ra0 + x1b) * 128];
        const float4 vB0a = fmt[(ra1 + x0a) * 128];
        const float4 vB1a = fmt[(ra1 + x1a) * 128];
        const float4 vB0b = fmt[(ra1 + x0b) * 128];
        const float4 vB1b = fmt[(ra1 + x1b) * 128];
        const float4 vC0a = fmt[(rb0 + x0a) * 128];
        const float4 vC1a = fmt[(rb0 + x1a) * 128];
        const float4 vC0b = fmt[(rb0 + x0b) * 128];
        const float4 vC1b = fmt[(rb0 + x1b) * 128];
        const float4 vD0a = fmt[(rb1 + x0a) * 128];
        const float4 vD1a = fmt[(rb1 + x1a) * 128];
        const float4 vD0b = fmt[(rb1 + x0b) * 128];
        const float4 vD1b = fmt[(rb1 + x1b) * 128];

        // Per-point bilinear weights (block-uniform scalars)
        // point (row pair a, col pair a): taps rows(ra0,ra1) x cols(x0a,x1a)
        const float4 s_aa = quad4(vA0a, vA1a, vB0a, vB1a,
                                  uya * uxa, uya * wxa, wya * uxa, wya * wxa);
        const float4 s_ab = quad4(vA0b, vA1b, vB0b, vB1b,
                                  uya * uxb, uya * wxb, wya * uxb, wya * wxb);
        const float4 s_ba = quad4(vC0a, vC1a, vD0a, vD1a,
                                  uyb * uxa, uyb * wxa, wyb * uxa, wyb * wxa);
        const float4 s_bb = quad4(vC0b, vC1b, vD0b, vD1b,
                                  uyb * uxb, uyb * wxb, wyb * uxb, wyb * wxb);

        outp[px * 128] = max4(max4(s_aa, s_ab), max4(s_ba, s_bb));
    }
}

extern "C" void kernel_launch(void* const* d_in, const int* in_sizes, int n_in,
                              void* d_out, int out_size)
{
    const float* fm   = (const float*)d_in[0];   // feature_maps [1,38,50,512]
    const float* rois = (const float*)d_in[1];   // [512,5]
    float* out = (float*)d_out;                  // [1,512,7,7,512]

    dim3 grid(POOL, N_ROI);
    roi_pool_kernel<<<grid, 128>>>(fm, rois, out);
}

// round 5
// speedup vs baseline: 1.7195x; 1.1996x over previous
#include <cuda_runtime.h>

#define FM_H 38
#define FM_W 50
#define N_ROI 512
#define POOL 7

__device__ __forceinline__ float4 quad4(float4 a, float4 b, float4 c, float4 d,
                                        float w0, float w1, float w2, float w3) {
    float4 r;
    r.x = fmaf(d.x, w3, fmaf(c.x, w2, fmaf(b.x, w1, a.x * w0)));
    r.y = fmaf(d.y, w3, fmaf(c.y, w2, fmaf(b.y, w1, a.y * w0)));
    r.z = fmaf(d.z, w3, fmaf(c.z, w2, fmaf(b.z, w1, a.z * w0)));
    r.w = fmaf(d.w, w3, fmaf(c.w, w2, fmaf(b.w, w1, a.w * w0)));
    return r;
}

__device__ __forceinline__ float4 max4(float4 a, float4 b) {
    float4 r;
    r.x = fmaxf(a.x, b.x);
    r.y = fmaxf(a.y, b.y);
    r.z = fmaxf(a.z, b.z);
    r.w = fmaxf(a.w, b.w);
    return r;
}

// MODE 0: 2 distinct fm rows (r0,r1). Point-pair b reads rows (r0,r1) with
//         folded weights (wbP,wbQ).
// MODE 1: 3 distinct fm rows (r0,r1,r2). Pair b reads rows (r1,r2).
// MODE 2: 4 distinct fm rows. Pair b reads rows (r2,r3).
template <int MODE>
__device__ __forceinline__ void run_row(
    const float4* __restrict__ fmt, float4* __restrict__ outp,
    float x1n, float dx,
    int r0, int r1, int r2, int r3,
    float waP, float waQ,      // row weights for pair a (rows r0,r1)
    float wbP, float wbQ)      // row weights for pair b (rows per MODE)
{
#pragma unroll
    for (int px = 0; px < POOL; ++px) {
        // x taps for the two crop cols of this pooled cell (block-uniform)
        int x0a, x1a, x0b, x1b;
        float wxa, wxb;
        {
            const float txa = (float)(2 * px) * (1.0f / 13.0f);
            const float xsa = (x1n + txa * dx) * (float)(FM_W - 1);
            const float xfa = floorf(xsa);
            int x0 = (int)xfa; x0 = min(max(x0, 0), FM_W - 1);
            x0a = x0; x1a = min(x0 + 1, FM_W - 1); wxa = xsa - xfa;

            const float txb = (float)(2 * px + 1) * (1.0f / 13.0f);
            const float xsb = (x1n + txb * dx) * (float)(FM_W - 1);
            const float xfb = floorf(xsb);
            int x1 = (int)xfb; x1 = min(max(x1, 0), FM_W - 1);
            x0b = x1; x1b = min(x1 + 1, FM_W - 1); wxb = xsb - xfb;
        }
        const float uxa = 1.0f - wxa;
        const float uxb = 1.0f - wxb;

        // Unconditional batched loads: (2 + MODE distinct rows) x 4 cols
        const float4 vA0a = fmt[(r0 + x0a) * 128];
        const float4 vA1a = fmt[(r0 + x1a) * 128];
        const float4 vA0b = fmt[(r0 + x0b) * 128];
        const float4 vA1b = fmt[(r0 + x1b) * 128];
        const float4 vB0a = fmt[(r1 + x0a) * 128];
        const float4 vB1a = fmt[(r1 + x1a) * 128];
        const float4 vB0b = fmt[(r1 + x0b) * 128];
        const float4 vB1b = fmt[(r1 + x1b) * 128];

        float4 vC0a, vC1a, vC0b, vC1b;   // pair-b source row P
        float4 vD0a, vD1a, vD0b, vD1b;   // pair-b source row Q
        if (MODE == 0) {
            vC0a = vA0a; vC1a = vA1a; vC0b = vA0b; vC1b = vA1b;
            vD0a = vB0a; vD1a = vB1a; vD0b = vB0b; vD1b = vB1b;
        } else if (MODE == 1) {
            vC0a = vB0a; vC1a = vB1a; vC0b = vB0b; vC1b = vB1b;
            vD0a = fmt[(r2 + x0a) * 128];
            vD1a = fmt[(r2 + x1a) * 128];
            vD0b = fmt[(r2 + x0b) * 128];
            vD1b = fmt[(r2 + x1b) * 128];
        } else {
            vC0a = fmt[(r2 + x0a) * 128];
            vC1a = fmt[(r2 + x1a) * 128];
            vC0b = fmt[(r2 + x0b) * 128];
            vC1b = fmt[(r2 + x1b) * 128];
            vD0a = fmt[(r3 + x0a) * 128];
            vD1a = fmt[(r3 + x1a) * 128];
            vD0b = fmt[(r3 + x0b) * 128];
            vD1b = fmt[(r3 + x1b) * 128];
        }

        const float4 s_aa = quad4(vA0a, vA1a, vB0a, vB1a,
                                  waP * uxa, waP * wxa, waQ * uxa, waQ * wxa);
        const float4 s_ab = quad4(vA0b, vA1b, vB0b, vB1b,
                                  waP * uxb, waP * wxb, waQ * uxb, waQ * wxb);
        const float4 s_ba = quad4(vC0a, vC1a, vD0a, vD1a,
                                  wbP * uxa, wbP * wxa, wbQ * uxa, wbQ * wxa);
        const float4 s_bb = quad4(vC0b, vC1b, vD0b, vD1b,
                                  wbP * uxb, wbP * wxb, wbQ * uxb, wbQ * wxb);

        outp[px * 128] = max4(max4(s_aa, s_ab), max4(s_ba, s_bb));
    }
}

// One block per (pooled_row, roi). 128 threads x float4 = 512 channels.
// Row-tap dedup: the 4 bilinear y-rows of a pooled row often collapse to
// 2 or 3 distinct fm rows; this is block-uniform, so dispatch once into a
// specialized body (8/12/16 loads per cell) with scalar row-weight folding.
__global__ __launch_bounds__(128) void roi_pool_kernel(
    const float* __restrict__ fm,     // [38,50,512]
    const float* __restrict__ rois,   // [512,5] (0, x1, y1, x2, y2)
    float* __restrict__ out)          // [512,7,7,512]
{
    const int py  = blockIdx.x;       // 0..6
    const int roi = blockIdx.y;       // 0..511
    const int t   = threadIdx.x;      // channel group: c = 4*t

    const float* r = rois + roi * 5;
    const float x1n = r[1] * (1.0f / 800.0f);
    const float y1n = r[2] * (1.0f / 600.0f);
    const float x2n = r[3] * (1.0f / 800.0f);
    const float y2n = r[4] * (1.0f / 600.0f);
    const float dy = y2n - y1n;
    const float dx = x2n - x1n;

    // y taps for the two crop rows of this pooled row (block-uniform)
    int ra0, ra1, rb0, rb1;           // fm row offsets (row * FM_W)
    float wya, wyb;
    {
        const float tya = (float)(2 * py) * (1.0f / 13.0f);
        const float ysa = (y1n + tya * dy) * (float)(FM_H - 1);
        const float yfa = floorf(ysa);
        int y0 = (int)yfa; y0 = min(max(y0, 0), FM_H - 1);
        ra0 = y0 * FM_W;
        ra1 = min(y0 + 1, FM_H - 1) * FM_W;
        wya = ysa - yfa;

        const float tyb = (float)(2 * py + 1) * (1.0f / 13.0f);
        const float ysb = (y1n + tyb * dy) * (float)(FM_H - 1);
        const float yfb = floorf(ysb);
        int y1 = (int)yfb; y1 = min(max(y1, 0), FM_H - 1);
        rb0 = y1 * FM_W;
        rb1 = min(y1 + 1, FM_H - 1) * FM_W;
        wyb = ysb - yfb;
    }
    const float uya = 1.0f - wya;
    const float uyb = 1.0f - wyb;

    const float4* fmt = (const float4*)fm + t;
    float4* outp = (float4*)out + (size_t)((roi * POOL + py) * POOL) * 128 + t;

    // Row dedup dispatch (block-uniform branch, fixed for all 7 cells).
    if (rb0 == ra0) {
        // rows b identical to rows a (rb1 == ra1 follows)
        run_row<0>(fmt, outp, x1n, dx, ra0, ra1, 0, 0,
                   uya, wya, uyb, wyb);
    } else if (rb0 == ra1) {
        if (rb1 == rb0) {
            // both b taps land on row ra1
            run_row<0>(fmt, outp, x1n, dx, ra0, ra1, 0, 0,
                       uya, wya, 0.0f, uyb + wyb);
        } else {
            // rows {ra0, ra1, rb1}; pair b uses (ra1, rb1)
            run_row<1>(fmt, outp, x1n, dx, ra0, ra1, rb1, 0,
                       uya, wya, uyb, wyb);
        }
    } else {
        // fully distinct (or rb1==rb0 clamp: duplicate load, still correct)
        run_row<2>(fmt, outp, x1n, dx, ra0, ra1, rb0, rb1,
                   uya, wya, uyb, wyb);
    }
}

extern "C" void kernel_launch(void* const* d_in, const int* in_sizes, int n_in,
                              void* d_out, int out_size)
{
    const float* fm   = (const float*)d_in[0];   // feature_maps [1,38,50,512]
    const float* rois = (const float*)d_in[1];   // [512,5]
    float* out = (float*)d_out;                  // [1,512,7,7,512]

    dim3 grid(POOL, N_ROI);
    roi_pool_kernel<<<grid, 128>>>(fm, rois, out);
}